// round 15
// baseline (speedup 1.0000x reference)
#include <cuda_runtime.h>
#include <cuda_fp16.h>
#include <mma.h>
#include <cstdint>

using namespace nvcuda;

// ---------------- problem constants ----------------
#define BB 4
#define TT 2048
#define DM 1024
#define HH 4
#define DKd 128
#define DVd 256
#define HDK 512     // H*DK
#define HDV 1024    // H*DV
#define BT  8192    // B*T tokens
#define CH  64      // chunk
#define NC  32      // chunks per sequence
#define NCHUNK 128  // total chunks (B*NC)
#define LR 16       // gate low rank
#define GNORM 16.0f
#define EPS 1e-5f
#define PERSIST_CTAS 304   // 152 SMs x 2

// ---------------- scratch ----------------
__device__ __half d_xh [BT * DM];
__device__ __half d_Wqh[DM * HDK];
__device__ __half d_Wkh[DM * HDK];
__device__ __half d_Wvh[DM * HDV];
__device__ __half d_Wgh[DM * HDV];
__device__ __half d_Woh[HDV * DM];
__device__ __half d_yh [BT * HDV];
__device__ __half d_qgh[BT * HDK];
__device__ __half d_kgh[BT * HDK];
__device__ __half d_Ah [NCHUNK * HH * CH * CH];
__device__ float d_W1t [LR * DM];
__device__ float d_q   [BT * HDK];
__device__ float d_k   [BT * HDK];
__device__ float d_v   [BT * HDV];
__device__ float d_g   [BT * HDV];
__device__ float d_gk  [BT * HDK];
__device__ float d_glast[NCHUNK * HDK];
__device__ float d_o   [BT * HDV];

// ---------------- helpers ----------------
__device__ __forceinline__ float rtf32(float x) {
    return wmma::__float_to_tf32(x);
}

typedef wmma::fragment<wmma::matrix_a, 16, 16, 8, wmma::precision::tf32, wmma::row_major> FragA;
typedef wmma::fragment<wmma::matrix_b, 16, 16, 8, wmma::precision::tf32, wmma::col_major> FragBT;
typedef wmma::fragment<wmma::accumulator, 16, 16, 8, float> FragC;

typedef wmma::fragment<wmma::matrix_a, 16, 16, 16, __half, wmma::row_major> FragAh;
typedef wmma::fragment<wmma::matrix_a, 16, 16, 16, __half, wmma::col_major> FragAhT;
typedef wmma::fragment<wmma::matrix_b, 16, 16, 16, __half, wmma::row_major> FragBh;
typedef wmma::fragment<wmma::accumulator, 16, 16, 16, float> FragCh;

__device__ __forceinline__ uint32_t smem_u32(const void* p) {
    return (uint32_t)__cvta_generic_to_shared(p);
}
__device__ __forceinline__ void cpasync16(void* dst, const void* src) {
    asm volatile("cp.async.cg.shared.global [%0], [%1], 16;\n"
                 :: "r"(smem_u32(dst)), "l"(src));
}
__device__ __forceinline__ void cp_commit() {
    asm volatile("cp.async.commit_group;\n");
}

// ---------------- float -> half conversion ----------------
__device__ __forceinline__ void f2h_body(const float4* in, uint2* out, int i) {
    float4 a = in[i];
    __half2 lo = __floats2half2_rn(a.x, a.y);
    __half2 hi = __floats2half2_rn(a.z, a.w);
    uint2 p;
    p.x = *(uint32_t*)&lo;
    p.y = *(uint32_t*)&hi;
    out[i] = p;
}

__global__ __launch_bounds__(256) void f2h_kernel(
    const float4* __restrict__ in, uint2* __restrict__ out, int n4)
{
    int i = blockIdx.x * 256 + threadIdx.x;
    if (i >= n4) return;
    f2h_body(in, out, i);
}

__global__ __launch_bounds__(256) void f2h_multi_kernel(
    const float4* i0, uint2* o0, int n0,
    const float4* i1, uint2* o1, int n1,
    const float4* i2, uint2* o2, int n2,
    const float4* i3, uint2* o3, int n3,
    const float4* i4, uint2* o4, int n4)
{
    const float4* in; uint2* out; int n;
    switch (blockIdx.y) {
        case 0: in = i0; out = o0; n = n0; break;
        case 1: in = i1; out = o1; n = n1; break;
        case 2: in = i2; out = o2; n = n2; break;
        case 3: in = i3; out = o3; n = n3; break;
        default: in = i4; out = o4; n = n4; break;
    }
    int i = blockIdx.x * 256 + threadIdx.x;
    if (i >= n) return;
    f2h_body(in, out, i);
}

// ---------------- W1 transpose ----------------
__global__ __launch_bounds__(256) void w1_transpose_kernel(
    const float* __restrict__ W1, float* __restrict__ W1t)
{
    int i = blockIdx.x * 256 + threadIdx.x;
    int n = i >> 10;
    int j = i & 1023;
    W1t[i] = W1[j * LR + n];
}

// ---------------- fp16 GEMM core: CTA 128x128, 256 threads, BK=32 ----------------
#define AS_STRIDE 40
#define BS_STRIDE 136
#define STAGE_HALFS (128 * AS_STRIDE + 32 * BS_STRIDE)   // 9472
#define GEMM_SMEM_BYTES (3 * STAGE_HALFS * 2)            // 56832

__device__ __forceinline__ void gemm_load_tile_h(
    __half* sm, int buf, const __half* A, int lda, const __half* B, int ldb, int it, int tid)
{
    __half* As = sm + buf * STAGE_HALFS;
    __half* Bs = As + 128 * AS_STRIDE;
    const __half* Ab = A + it * 32;
    const __half* Bb = B + (size_t)it * 32 * ldb;
#pragma unroll
    for (int i = tid; i < 512; i += 256) {
        int r = i >> 2, c = i & 3;
        cpasync16(&As[r * AS_STRIDE + c * 8], Ab + (size_t)r * lda + c * 8);
    }
#pragma unroll
    for (int i = tid; i < 512; i += 256) {
        int r = i >> 4, c = i & 15;
        cpasync16(&Bs[r * BS_STRIDE + c * 8], Bb + (size_t)r * ldb + c * 8);
    }
    cp_commit();
}

__device__ __forceinline__ void gemm128x128_fp16(
    const __half* __restrict__ A, int lda,
    const __half* __restrict__ B, int ldb,
    float* __restrict__ C, int ldc,
    int K, __half* sm)
{
    const int tid = threadIdx.x;
    const int w = tid >> 5;
    const int wr = w >> 1;
    const int wc = w & 1;

    FragCh acc[2][4];
#pragma unroll
    for (int r = 0; r < 2; r++)
#pragma unroll
        for (int c = 0; c < 4; c++) wmma::fill_fragment(acc[r][c], 0.0f);

    const int ntiles = K / 32;

    gemm_load_tile_h(sm, 0, A, lda, B, ldb, 0, tid);
    gemm_load_tile_h(sm, 1, A, lda, B, ldb, 1, tid);

    for (int it = 0; it < ntiles; it++) {
        if (it < ntiles - 1) {
            asm volatile("cp.async.wait_group 1;\n");
        } else {
            asm volatile("cp.async.wait_group 0;\n");
        }
        __syncthreads();
        if (it + 2 < ntiles)
            gemm_load_tile_h(sm, (it + 2) % 3, A, lda, B, ldb, it + 2, tid);

        __half* Ac = sm + (it % 3) * STAGE_HALFS;
        __half* Bc = Ac + 128 * AS_STRIDE;
#pragma unroll
        for (int kk = 0; kk < 32; kk += 16) {
            FragAh af[2];
            FragBh bf[4];
#pragma unroll
            for (int r = 0; r < 2; r++)
                wmma::load_matrix_sync(af[r], &Ac[(wr * 32 + r * 16) * AS_STRIDE + kk], AS_STRIDE);
#pragma unroll
            for (int c = 0; c < 4; c++)
                wmma::load_matrix_sync(bf[c], &Bc[kk * BS_STRIDE + wc * 64 + c * 16], BS_STRIDE);
#pragma unroll
            for (int r = 0; r < 2; r++)
#pragma unroll
                for (int c = 0; c < 4; c++)
                    wmma::mma_sync(acc[r][c], af[r], bf[c], acc[r][c]);
        }
    }
    __syncthreads();

#pragma unroll
    for (int r = 0; r < 2; r++)
#pragma unroll
        for (int c = 0; c < 4; c++)
            wmma::store_matrix_sync(
                C + (size_t)(wr * 32 + r * 16) * ldc + wc * 64 + c * 16,
                acc[r][c], ldc, wmma::mem_row_major);
}

// ---------------- fused q/k/v/g projections (persistent CTAs) ----------------
// tiles: tn 0..23 (0..3 q, 4..7 k, 8..15 v, 16..23 g) x tm 0..63
__global__ __launch_bounds__(256, 2) void proj_qkvg_kernel(
    const __half* __restrict__ xh,
    const __half* __restrict__ Wq, const __half* __restrict__ Wk,
    const __half* __restrict__ Wv, const __half* __restrict__ Wg,
    float* __restrict__ q, float* __restrict__ k,
    float* __restrict__ v, float* __restrict__ g)
{
    extern __shared__ __half smh[];
    for (int t = blockIdx.x; t < 24 * 64; t += gridDim.x) {
        const int bn = t % 24;
        const int bm = t / 24;
        const __half* B;
        float* C;
        int n0, ldn;
        if (bn < 4)       { B = Wq; C = q; n0 = bn;      ldn = HDK; }
        else if (bn < 8)  { B = Wk; C = k; n0 = bn - 4;  ldn = HDK; }
        else if (bn < 16) { B = Wv; C = v; n0 = bn - 8;  ldn = HDV; }
        else              { B = Wg; C = g; n0 = bn - 16; ldn = HDV; }
        gemm128x128_fp16(xh + (size_t)bm * 128 * DM, DM,
                         B + n0 * 128, ldn,
                         C + (size_t)bm * 128 * ldn + n0 * 128, ldn,
                         DM, smh);
        __syncthreads();
    }
}

// ---------------- output projection (persistent CTAs) ----------------
__global__ __launch_bounds__(256, 2) void gemm_wo_kernel(
    const __half* __restrict__ yh, const __half* __restrict__ Wo, float* __restrict__ out)
{
    extern __shared__ __half smh[];
    for (int t = blockIdx.x; t < 8 * 64; t += gridDim.x) {
        const int bn = t % 8;
        const int bm = t / 8;
        gemm128x128_fp16(yh + (size_t)bm * 128 * HDV, HDV,
                         Wo + bn * 128, DM,
                         out + (size_t)bm * 128 * DM + bn * 128,
                         DM, HDV, smh);
        __syncthreads();
    }
}

// ---------------- fused low-rank gate ----------------
__global__ __launch_bounds__(256) void gk_fused_kernel(
    const float* __restrict__ x, const float* __restrict__ W1t,
    const float* __restrict__ W2, const float* __restrict__ bias,
    float* __restrict__ gk)
{
    int t = blockIdx.x * 8 + (threadIdx.x >> 5);
    int lane = threadIdx.x & 31;
    const float* xr = x + (size_t)t * DM;

    float xreg[32];
#pragma unroll
    for (int i = 0; i < 32; i++) xreg[i] = xr[lane + 32 * i];

    float acc[LR];
#pragma unroll
    for (int n = 0; n < LR; n++) {
        const float* wrow = W1t + (size_t)n * DM;
        float s = 0.0f;
#pragma unroll
        for (int i = 0; i < 32; i++) s += xreg[i] * wrow[lane + 32 * i];
        acc[n] = s;
    }
#pragma unroll
    for (int n = 0; n < LR; n++) {
#pragma unroll
        for (int off = 16; off > 0; off >>= 1)
            acc[n] += __shfl_xor_sync(0xffffffff, acc[n], off);
    }

    float* gkt = gk + (size_t)t * HDK;
#pragma unroll
    for (int j = 0; j < 16; j++) {
        int n = j * 32 + lane;
        float a = bias[n];
#pragma unroll
        for (int kx = 0; kx < LR; kx++) a += acc[kx] * W2[kx * HDK + n];
        float ls = fminf(a, 0.0f) - log1pf(expf(-fabsf(a)));
        gkt[n] = ls * (1.0f / GNORM);
    }
}

// ---------------- FUSED decay + intra-A ----------------
#define DA_STRIDE 132
#define DA_SMEM_BYTES ((2 * 64 * DA_STRIDE + 64 * 72) * 4)   // 86016

__global__ __launch_bounds__(256) void decayA_kernel(
    const float* __restrict__ q, const float* __restrict__ k, const float* __restrict__ gk,
    __half* __restrict__ qgh, __half* __restrict__ kgh,
    float* __restrict__ glast, __half* __restrict__ Ah)
{
    extern __shared__ float dsm[];
    float* qs = dsm;
    float* ks = dsm + 64 * DA_STRIDE;
    float* As = ks + 64 * DA_STRIDE;

    const int chh = blockIdx.x;
    const int c = chh >> 2, h = chh & 3;
    const int tid = threadIdx.x, w = tid >> 5;

    if (tid < 128) {
        const int col = tid;
        size_t base = (size_t)c * CH * HDK + h * DKd + col;
        float tot = 0.0f;
#pragma unroll 8
        for (int i = 0; i < CH; i++) tot += gk[base + (size_t)i * HDK];
        glast[(size_t)c * HDK + h * DKd + col] = __expf(tot);
        const float scale = 0.088388347648318447f;   // 128^-0.5
        float run = 0.0f;
#pragma unroll 4
        for (int i = 0; i < CH; i++) {
            size_t idx = base + (size_t)i * HDK;
            run += gk[idx];
            float qv = q[idx] * __expf(run) * scale;
            float kgv = k[idx] * __expf(tot - run);
            qs[i * DA_STRIDE + col] = rtf32(qv);
            ks[i * DA_STRIDE + col] = rtf32(k[idx] * __expf(-run));
            qgh[idx] = __float2half(qv);
            kgh[idx] = __float2half(kgv);
        }
    }
    __syncthreads();

#pragma unroll
    for (int tIdx = w * 2; tIdx < w * 2 + 2; tIdx++) {
        int ti = tIdx >> 2, tj = tIdx & 3;
        FragC acc;
        wmma::fill_fragment(acc, 0.0f);
#pragma unroll
        for (int kk = 0; kk < DKd; kk += 8) {
            FragA a; FragBT b;
            wmma::load_matrix_sync(a, &qs[(ti * 16) * DA_STRIDE + kk], DA_STRIDE);
            wmma::load_matrix_sync(b, &ks[(tj * 16) * DA_STRIDE + kk], DA_STRIDE);
            wmma::mma_sync(acc, a, b, acc);
        }
        wmma::store_matrix_sync(&As[(ti * 16) * 72 + tj * 16], acc, 72, wmma::mem_row_major);
    }
    __syncthreads();
    __half* Ab = Ah + (size_t)chh * CH * CH;
    for (int i = tid; i < 64 * 64; i += 256) {
        int r = i >> 6, cc = i & 63;
        Ab[i] = (cc > r) ? __float2half(0.0f) : __float2half(As[r * 72 + cc]);
    }
}

// ---------------- FUSED chunkwise GLA: 256 CTAs, dv-block = 16 ----------------
#define S2_STRIDE 20     // fp32, 16 cols + 4 pad
#define SH2_STRIDE 24    // halves
#define VH2_STRIDE 24    // halves
#define VF2_STRIDE 20    // fp32 prefetch
#define U2_STRIDE 20
#define FUSED_SMEM_BYTES ((128*S2_STRIDE + 2*64*VF2_STRIDE + 128*U2_STRIDE + 2*128) * 4 \
                          + (128*SH2_STRIDE + 64*VH2_STRIDE) * 2)

__global__ __launch_bounds__(256) void gla_fused_kernel(
    const __half* __restrict__ Amat, const __half* __restrict__ qgh,
    const __half* __restrict__ kgh, const float* __restrict__ v,
    const float* __restrict__ glast, float* __restrict__ o)
{
    extern __shared__ char smraw[];
    float*  Ssm  = (float*)smraw;                    // 128 x 20
    float*  Vf   = Ssm + 128 * S2_STRIDE;            // 2 x 64 x 20
    float*  Us   = Vf + 2 * 64 * VF2_STRIDE;         // 128 x 20
    float*  sglf = Us + 128 * U2_STRIDE;             // 2 x 128
    __half* Sh   = (__half*)(sglf + 2 * 128);        // 128 x 24
    __half* Vsh  = Sh + 128 * SH2_STRIDE;            // 64 x 24

    const int id = blockIdx.x;                       // 0..255
    const int b = id >> 6, h = (id >> 4) & 3, dvb = id & 15;
    const int tid = threadIdx.x, w = tid >> 5;

    for (int i = tid; i < 128 * S2_STRIDE; i += 256) Ssm[i] = 0.0f;
    for (int i = tid; i < 128 * SH2_STRIDE / 2; i += 256)
        *((__half2*)Sh + i) = __half2half2(__float2half(0.0f));

    auto issue_load = [&](int n, int buf) {
        const float* vb = v + (size_t)(b * NC + n) * CH * HDV + h * DVd + dvb * 16;
        const float* gl = glast + (size_t)(b * NC + n) * HDK + h * DKd;
        {
            int r = tid >> 2, c = tid & 3;           // 64 rows x 4 chunks of 4 floats
            cpasync16(Vf + buf * 64 * VF2_STRIDE + r * VF2_STRIDE + c * 4,
                      vb + (size_t)r * HDV + c * 4);
        }
        if (tid < 32) cpasync16(sglf + buf * 128 + tid * 4, gl + tid * 4);
        cp_commit();
    };

    issue_load(0, 0);

    for (int n = 0; n < NC; n++) {
        const int buf = n & 1;
        const int c = b * NC + n;
        const int ch = c * HH + h;
        const size_t t0 = (size_t)c * CH;
        const __half* qgb = qgh + t0 * HDK + h * DKd;
        const __half* kgb = kgh + t0 * HDK + h * DKd;
        const __half* Ab  = Amat + (size_t)ch * CH * CH;
        float* ob         = o + t0 * HDV + h * DVd + dvb * 16;

        asm volatile("cp.async.wait_group 0;\n");
        __syncthreads();   // V(n)/sgl(n) arrived; prev S update complete

        if (n + 1 < NC) issue_load(n + 1, buf ^ 1);

        // convert Vf[buf] -> Vsh (fp16): 64 x 16, 4 halves per thread
        {
            int r = tid >> 2, c4 = tid & 3;
            const float* src = Vf + buf * 64 * VF2_STRIDE + r * VF2_STRIDE + c4 * 4;
            float4 a4 = *(const float4*)src;
            __half2 h0 = __floats2half2_rn(a4.x, a4.y);
            __half2 h1 = __floats2half2_rn(a4.z, a4.w);
            uint2 u;
            u.x = *(uint32_t*)&h0; u.y = *(uint32_t*)&h1;
            *(uint2*)&Vsh[r * VH2_STRIDE + c4 * 4] = u;
        }
        __syncthreads();

        if (w < 4) {
            // ---- o = A @ Vsh + qg @ Sh  (64x16; warp -> one 16x16 frag) ----
            FragCh acc2;
            wmma::fill_fragment(acc2, 0.0f);
#pragma unroll
            for (int kk = 0; kk < CH; kk += 16) {
                FragAh a; FragBh bf;
                wmma::load_matrix_sync(a, Ab + (size_t)(w * 16) * CH + kk, CH);
                wmma::load_matrix_sync(bf, &Vsh[kk * VH2_STRIDE], VH2_STRIDE);
                wmma::mma_sync(acc2, a, bf, acc2);
            }
#pragma unroll
            for (int kk = 0; kk < DKd; kk += 16) {
                FragAh a; FragBh bf;
                wmma::load_matrix_sync(a, qgb + (size_t)(w * 16) * HDK + kk, HDK);
                wmma::load_matrix_sync(bf, &Sh[kk * SH2_STRIDE], SH2_STRIDE);
                wmma::mma_sync(acc2, a, bf, acc2);
            }
            wmma::store_matrix_sync(ob + (size_t)(w * 16) * HDV, acc2, HDV, wmma::mem_row_major);
        } else {
            // ---- U = kg^T (128x16) @ Vsh (64x16): warp wu -> rows 32wu..32wu+31 ----
            const int wu = w - 4;
            FragCh acc4[2];
#pragma unroll
            for (int r = 0; r < 2; r++) wmma::fill_fragment(acc4[r], 0.0f);
#pragma unroll
            for (int kk = 0; kk < CH; kk += 16) {
                FragAhT a[2];
                FragBh bf;
#pragma unroll
                for (int r = 0; r < 2; r++)
                    wmma::load_matrix_sync(a[r], kgb + (size_t)kk * HDK + (2 * wu + r) * 16, HDK);
                wmma::load_matrix_sync(bf, &Vsh[kk * VH2_STRIDE], VH2_STRIDE);
#pragma unroll
                for (int r = 0; r < 2; r++)
                    wmma::mma_sync(acc4[r], a[r], bf, acc4[r]);
            }
#pragma unroll
            for (int r = 0; r < 2; r++)
                wmma::store_matrix_sync(&Us[((2 * wu + r) * 16) * U2_STRIDE], acc4[r],
                                        U2_STRIDE, wmma::mem_row_major);
        }
        __syncthreads();

        // ---- S = S * diag(gl) + U  (128x16) ----
        const float* sgl = sglf + buf * 128;
#pragma unroll
        for (int j = 0; j < 8; j++) {
            int i = j * 256 + tid;
            int r = i >> 4, cc = i & 15;
            float s = Ssm[r * S2_STRIDE + cc] * sgl[r] + Us[r * U2_STRIDE + cc];
            Ssm[r * S2_STRIDE + cc] = s;
            Sh[r * SH2_STRIDE + cc] = __float2half(s);
        }
    }
}

// ---------------- gated RMSNorm (emits fp16 y) ----------------
__global__ __launch_bounds__(256) void norm_gate_kernel(
    const float* __restrict__ o, const float* __restrict__ g,
    const float* __restrict__ gnw, __half* __restrict__ yh)
{
    int row = blockIdx.x * 8 + (threadIdx.x >> 5);
    int lane = threadIdx.x & 31;
    size_t base = (size_t)row * DVd;
    float v[8];
    float ss = 0.0f;
#pragma unroll
    for (int j = 0; j < 8; j++) {
        v[j] = o[base + lane + j * 32];
        ss += v[j] * v[j];
    }
#pragma unroll
    for (int off = 16; off > 0; off >>= 1)
        ss += __shfl_xor_sync(0xffffffff, ss, off);
    float r = rsqrtf(ss * (1.0f / DVd) + EPS);
#pragma unroll
    for (int j = 0; j < 8; j++) {
        int dv = lane + j * 32;
        float gv = g[base + dv];
        float sw = gv / (1.0f + expf(-gv));
        yh[base + dv] = __float2half(v[j] * r * gnw[dv] * sw);
    }
}

// ---------------- launch ----------------
extern "C" void kernel_launch(void* const* d_in, const int* in_sizes, int n_in,
                              void* d_out, int out_size)
{
    const float* x    = (const float*)d_in[0];
    const float* Wq   = (const float*)d_in[1];
    const float* Wk   = (const float*)d_in[2];
    const float* Wv   = (const float*)d_in[3];
    const float* Wg   = (const float*)d_in[4];
    const float* Wgk1 = (const float*)d_in[5];
    const float* Wgk2 = (const float*)d_in[6];
    const float* bgk2 = (const float*)d_in[7];
    const float* Wo   = (const float*)d_in[8];
    const float* gnw  = (const float*)d_in[9];
    float* out = (float*)d_out;

    __half *xh, *Wqh, *Wkh, *Wvh, *Wgh, *Woh, *yh, *qgh, *kgh, *Ah;
    float *W1t, *q, *k, *v, *g, *gk, *glast, *o;
    cudaGetSymbolAddress((void**)&xh, d_xh);
    cudaGetSymbolAddress((void**)&Wqh, d_Wqh);
    cudaGetSymbolAddress((void**)&Wkh, d_Wkh);
    cudaGetSymbolAddress((void**)&Wvh, d_Wvh);
    cudaGetSymbolAddress((void**)&Wgh, d_Wgh);
    cudaGetSymbolAddress((void**)&Woh, d_Woh);
    cudaGetSymbolAddress((void**)&yh, d_yh);
    cudaGetSymbolAddress((void**)&qgh, d_qgh);
    cudaGetSymbolAddress((void**)&kgh, d_kgh);
    cudaGetSymbolAddress((void**)&Ah, d_Ah);
    cudaGetSymbolAddress((void**)&W1t, d_W1t);
    cudaGetSymbolAddress((void**)&q, d_q);
    cudaGetSymbolAddress((void**)&k, d_k);
    cudaGetSymbolAddress((void**)&v, d_v);
    cudaGetSymbolAddress((void**)&g, d_g);
    cudaGetSymbolAddress((void**)&gk, d_gk);
    cudaGetSymbolAddress((void**)&glast, d_glast);
    cudaGetSymbolAddress((void**)&o, d_o);

    cudaFuncSetAttribute(proj_qkvg_kernel,
                         cudaFuncAttributeMaxDynamicSharedMemorySize, GEMM_SMEM_BYTES);
    cudaFuncSetAttribute(gemm_wo_kernel,
                         cudaFuncAttributeMaxDynamicSharedMemorySize, GEMM_SMEM_BYTES);
    cudaFuncSetAttribute(gla_fused_kernel,
                         cudaFuncAttributeMaxDynamicSharedMemorySize, FUSED_SMEM_BYTES);
    cudaFuncSetAttribute(decayA_kernel,
                         cudaFuncAttributeMaxDynamicSharedMemorySize, DA_SMEM_BYTES);

    // conversions + W1 transpose
    f2h_kernel<<<(BT * DM / 4) / 256, 256>>>((const float4*)x, (uint2*)xh, BT * DM / 4);
    f2h_multi_kernel<<<dim3(1024, 5), 256>>>(
        (const float4*)Wq, (uint2*)Wqh, DM * HDK / 4,
        (const float4*)Wk, (uint2*)Wkh, DM * HDK / 4,
        (const float4*)Wv, (uint2*)Wvh, DM * HDV / 4,
        (const float4*)Wg, (uint2*)Wgh, DM * HDV / 4,
        (const float4*)Wo, (uint2*)Woh, HDV * DM / 4);
    w1_transpose_kernel<<<(LR * DM) / 256, 256>>>(Wgk1, W1t);

    // fused input projections (persistent, 2 CTAs/SM)
    proj_qkvg_kernel<<<PERSIST_CTAS, 256, GEMM_SMEM_BYTES>>>(xh, Wqh, Wkh, Wvh, Wgh, q, k, v, g);

    // fused low-rank gate path
    gk_fused_kernel<<<BT / 8, 256>>>(x, W1t, Wgk2, bgk2, gk);

    // FUSED decay + intra-A
    decayA_kernel<<<NCHUNK * HH, 256, DA_SMEM_BYTES>>>(q, k, gk, qgh, kgh, glast, Ah);

    // fused chunkwise GLA (256 CTAs, dv-block 16)
    gla_fused_kernel<<<BB * HH * 16, 256, FUSED_SMEM_BYTES>>>(Ah, qgh, kgh, v, glast, o);

    // gated RMSNorm + output projection (persistent)
    norm_gate_kernel<<<(BT * HH) / 8, 256>>>(o, g, gnw, yh);
    gemm_wo_kernel<<<PERSIST_CTAS, 256, GEMM_SMEM_BYTES>>>(yh, Woh, out);
}

// round 16
// speedup vs baseline: 1.0495x; 1.0495x over previous
#include <cuda_runtime.h>
#include <cuda_fp16.h>
#include <mma.h>
#include <cstdint>

using namespace nvcuda;

// ---------------- problem constants ----------------
#define BB 4
#define TT 2048
#define DM 1024
#define HH 4
#define DKd 128
#define DVd 256
#define HDK 512     // H*DK
#define HDV 1024    // H*DV
#define BT  8192    // B*T tokens
#define CH  64      // chunk
#define NC  32      // chunks per sequence
#define NCHUNK 128  // total chunks (B*NC)
#define LR 16       // gate low rank
#define GNORM 16.0f
#define EPS 1e-5f
#define PERSIST_CTAS 304   // 152 SMs x 2

// ---------------- scratch ----------------
__device__ __half d_xh [BT * DM];
__device__ __half d_Wqh[DM * HDK];
__device__ __half d_Wkh[DM * HDK];
__device__ __half d_Wvh[DM * HDV];
__device__ __half d_Wgh[DM * HDV];
__device__ __half d_Woh[HDV * DM];
__device__ __half d_yh [BT * HDV];
__device__ __half d_qgh[BT * HDK];
__device__ __half d_kgh[BT * HDK];
__device__ __half d_Ah [NCHUNK * HH * CH * CH];
__device__ float d_W1t [LR * DM];
__device__ float d_q   [BT * HDK];
__device__ float d_k   [BT * HDK];
__device__ float d_v   [BT * HDV];
__device__ float d_g   [BT * HDV];
__device__ float d_gk  [BT * HDK];
__device__ float d_glast[NCHUNK * HDK];
__device__ float d_o   [BT * HDV];

// ---------------- helpers ----------------
__device__ __forceinline__ float rtf32(float x) {
    return wmma::__float_to_tf32(x);
}

typedef wmma::fragment<wmma::matrix_a, 16, 16, 8, wmma::precision::tf32, wmma::row_major> FragA;
typedef wmma::fragment<wmma::matrix_b, 16, 16, 8, wmma::precision::tf32, wmma::col_major> FragBT;
typedef wmma::fragment<wmma::accumulator, 16, 16, 8, float> FragC;

typedef wmma::fragment<wmma::matrix_a, 16, 16, 16, __half, wmma::row_major> FragAh;
typedef wmma::fragment<wmma::matrix_a, 16, 16, 16, __half, wmma::col_major> FragAhT;
typedef wmma::fragment<wmma::matrix_b, 16, 16, 16, __half, wmma::row_major> FragBh;
typedef wmma::fragment<wmma::accumulator, 16, 16, 16, float> FragCh;

__device__ __forceinline__ uint32_t smem_u32(const void* p) {
    return (uint32_t)__cvta_generic_to_shared(p);
}
__device__ __forceinline__ void cpasync16(void* dst, const void* src) {
    asm volatile("cp.async.cg.shared.global [%0], [%1], 16;\n"
                 :: "r"(smem_u32(dst)), "l"(src));
}
__device__ __forceinline__ void cp_commit() {
    asm volatile("cp.async.commit_group;\n");
}

// ---------------- float -> half conversion ----------------
__device__ __forceinline__ void f2h_body(const float4* in, uint2* out, int i) {
    float4 a = in[i];
    __half2 lo = __floats2half2_rn(a.x, a.y);
    __half2 hi = __floats2half2_rn(a.z, a.w);
    uint2 p;
    p.x = *(uint32_t*)&lo;
    p.y = *(uint32_t*)&hi;
    out[i] = p;
}

__global__ __launch_bounds__(256) void f2h_kernel(
    const float4* __restrict__ in, uint2* __restrict__ out, int n4)
{
    int i = blockIdx.x * 256 + threadIdx.x;
    if (i >= n4) return;
    f2h_body(in, out, i);
}

__global__ __launch_bounds__(256) void f2h_multi_kernel(
    const float4* i0, uint2* o0, int n0,
    const float4* i1, uint2* o1, int n1,
    const float4* i2, uint2* o2, int n2,
    const float4* i3, uint2* o3, int n3,
    const float4* i4, uint2* o4, int n4)
{
    const float4* in; uint2* out; int n;
    switch (blockIdx.y) {
        case 0: in = i0; out = o0; n = n0; break;
        case 1: in = i1; out = o1; n = n1; break;
        case 2: in = i2; out = o2; n = n2; break;
        case 3: in = i3; out = o3; n = n3; break;
        default: in = i4; out = o4; n = n4; break;
    }
    int i = blockIdx.x * 256 + threadIdx.x;
    if (i >= n) return;
    f2h_body(in, out, i);
}

// ---------------- W1 transpose ----------------
__global__ __launch_bounds__(256) void w1_transpose_kernel(
    const float* __restrict__ W1, float* __restrict__ W1t)
{
    int i = blockIdx.x * 256 + threadIdx.x;
    int n = i >> 10;
    int j = i & 1023;
    W1t[i] = W1[j * LR + n];
}

// ---------------- fp16 GEMM core: CTA 128x128, 256 threads, BK=32 ----------------
#define AS_STRIDE 40
#define BS_STRIDE 136
#define STAGE_HALFS (128 * AS_STRIDE + 32 * BS_STRIDE)   // 9472
#define GEMM_SMEM_BYTES (3 * STAGE_HALFS * 2)            // 56832

__device__ __forceinline__ void gemm_load_tile_h(
    __half* sm, int buf, const __half* A, int lda, const __half* B, int ldb, int it, int tid)
{
    __half* As = sm + buf * STAGE_HALFS;
    __half* Bs = As + 128 * AS_STRIDE;
    const __half* Ab = A + it * 32;
    const __half* Bb = B + (size_t)it * 32 * ldb;
#pragma unroll
    for (int i = tid; i < 512; i += 256) {
        int r = i >> 2, c = i & 3;
        cpasync16(&As[r * AS_STRIDE + c * 8], Ab + (size_t)r * lda + c * 8);
    }
#pragma unroll
    for (int i = tid; i < 512; i += 256) {
        int r = i >> 4, c = i & 15;
        cpasync16(&Bs[r * BS_STRIDE + c * 8], Bb + (size_t)r * ldb + c * 8);
    }
    cp_commit();
}

__device__ __forceinline__ void gemm128x128_fp16(
    const __half* __restrict__ A, int lda,
    const __half* __restrict__ B, int ldb,
    float* __restrict__ C, int ldc,
    int K, __half* sm)
{
    const int tid = threadIdx.x;
    const int w = tid >> 5;
    const int wr = w >> 1;
    const int wc = w & 1;

    FragCh acc[2][4];
#pragma unroll
    for (int r = 0; r < 2; r++)
#pragma unroll
        for (int c = 0; c < 4; c++) wmma::fill_fragment(acc[r][c], 0.0f);

    const int ntiles = K / 32;

    gemm_load_tile_h(sm, 0, A, lda, B, ldb, 0, tid);
    gemm_load_tile_h(sm, 1, A, lda, B, ldb, 1, tid);

    for (int it = 0; it < ntiles; it++) {
        if (it < ntiles - 1) {
            asm volatile("cp.async.wait_group 1;\n");
        } else {
            asm volatile("cp.async.wait_group 0;\n");
        }
        __syncthreads();
        if (it + 2 < ntiles)
            gemm_load_tile_h(sm, (it + 2) % 3, A, lda, B, ldb, it + 2, tid);

        __half* Ac = sm + (it % 3) * STAGE_HALFS;
        __half* Bc = Ac + 128 * AS_STRIDE;
#pragma unroll
        for (int kk = 0; kk < 32; kk += 16) {
            FragAh af[2];
            FragBh bf[4];
#pragma unroll
            for (int r = 0; r < 2; r++)
                wmma::load_matrix_sync(af[r], &Ac[(wr * 32 + r * 16) * AS_STRIDE + kk], AS_STRIDE);
#pragma unroll
            for (int c = 0; c < 4; c++)
                wmma::load_matrix_sync(bf[c], &Bc[kk * BS_STRIDE + wc * 64 + c * 16], BS_STRIDE);
#pragma unroll
            for (int r = 0; r < 2; r++)
#pragma unroll
                for (int c = 0; c < 4; c++)
                    wmma::mma_sync(acc[r][c], af[r], bf[c], acc[r][c]);
        }
    }
    __syncthreads();

#pragma unroll
    for (int r = 0; r < 2; r++)
#pragma unroll
        for (int c = 0; c < 4; c++)
            wmma::store_matrix_sync(
                C + (size_t)(wr * 32 + r * 16) * ldc + wc * 64 + c * 16,
                acc[r][c], ldc, wmma::mem_row_major);
}

// ---------------- fused q/k/v/g projections (persistent CTAs) ----------------
__global__ __launch_bounds__(256, 2) void proj_qkvg_kernel(
    const __half* __restrict__ xh,
    const __half* __restrict__ Wq, const __half* __restrict__ Wk,
    const __half* __restrict__ Wv, const __half* __restrict__ Wg,
    float* __restrict__ q, float* __restrict__ k,
    float* __restrict__ v, float* __restrict__ g)
{
    extern __shared__ __half smh[];
    for (int t = blockIdx.x; t < 24 * 64; t += gridDim.x) {
        const int bn = t % 24;
        const int bm = t / 24;
        const __half* B;
        float* C;
        int n0, ldn;
        if (bn < 4)       { B = Wq; C = q; n0 = bn;      ldn = HDK; }
        else if (bn < 8)  { B = Wk; C = k; n0 = bn - 4;  ldn = HDK; }
        else if (bn < 16) { B = Wv; C = v; n0 = bn - 8;  ldn = HDV; }
        else              { B = Wg; C = g; n0 = bn - 16; ldn = HDV; }
        gemm128x128_fp16(xh + (size_t)bm * 128 * DM, DM,
                         B + n0 * 128, ldn,
                         C + (size_t)bm * 128 * ldn + n0 * 128, ldn,
                         DM, smh);
        __syncthreads();
    }
}

// ---------------- output projection (persistent CTAs) ----------------
__global__ __launch_bounds__(256, 2) void gemm_wo_kernel(
    const __half* __restrict__ yh, const __half* __restrict__ Wo, float* __restrict__ out)
{
    extern __shared__ __half smh[];
    for (int t = blockIdx.x; t < 8 * 64; t += gridDim.x) {
        const int bn = t % 8;
        const int bm = t / 8;
        gemm128x128_fp16(yh + (size_t)bm * 128 * HDV, HDV,
                         Wo + bn * 128, DM,
                         out + (size_t)bm * 128 * DM + bn * 128,
                         DM, HDV, smh);
        __syncthreads();
    }
}

// ---------------- fused low-rank gate ----------------
__global__ __launch_bounds__(256) void gk_fused_kernel(
    const float* __restrict__ x, const float* __restrict__ W1t,
    const float* __restrict__ W2, const float* __restrict__ bias,
    float* __restrict__ gk)
{
    int t = blockIdx.x * 8 + (threadIdx.x >> 5);
    int lane = threadIdx.x & 31;
    const float* xr = x + (size_t)t * DM;

    float xreg[32];
#pragma unroll
    for (int i = 0; i < 32; i++) xreg[i] = xr[lane + 32 * i];

    float acc[LR];
#pragma unroll
    for (int n = 0; n < LR; n++) {
        const float* wrow = W1t + (size_t)n * DM;
        float s = 0.0f;
#pragma unroll
        for (int i = 0; i < 32; i++) s += xreg[i] * wrow[lane + 32 * i];
        acc[n] = s;
    }
#pragma unroll
    for (int n = 0; n < LR; n++) {
#pragma unroll
        for (int off = 16; off > 0; off >>= 1)
            acc[n] += __shfl_xor_sync(0xffffffff, acc[n], off);
    }

    float* gkt = gk + (size_t)t * HDK;
#pragma unroll
    for (int j = 0; j < 16; j++) {
        int n = j * 32 + lane;
        float a = bias[n];
#pragma unroll
        for (int kx = 0; kx < LR; kx++) a += acc[kx] * W2[kx * HDK + n];
        float ls = fminf(a, 0.0f) - log1pf(expf(-fabsf(a)));
        gkt[n] = ls * (1.0f / GNORM);
    }
}

// ---------------- FUSED decay + intra-A ----------------
#define DA_STRIDE 132
#define DA_SMEM_BYTES ((2 * 64 * DA_STRIDE + 64 * 72) * 4)   // 86016

__global__ __launch_bounds__(256) void decayA_kernel(
    const float* __restrict__ q, const float* __restrict__ k, const float* __restrict__ gk,
    __half* __restrict__ qgh, __half* __restrict__ kgh,
    float* __restrict__ glast, __half* __restrict__ Ah)
{
    extern __shared__ float dsm[];
    float* qs = dsm;
    float* ks = dsm + 64 * DA_STRIDE;
    float* As = ks + 64 * DA_STRIDE;

    const int chh = blockIdx.x;
    const int c = chh >> 2, h = chh & 3;
    const int tid = threadIdx.x, w = tid >> 5;

    if (tid < 128) {
        const int col = tid;
        size_t base = (size_t)c * CH * HDK + h * DKd + col;
        float tot = 0.0f;
#pragma unroll 8
        for (int i = 0; i < CH; i++) tot += gk[base + (size_t)i * HDK];
        glast[(size_t)c * HDK + h * DKd + col] = __expf(tot);
        const float scale = 0.088388347648318447f;   // 128^-0.5
        float run = 0.0f;
#pragma unroll 4
        for (int i = 0; i < CH; i++) {
            size_t idx = base + (size_t)i * HDK;
            run += gk[idx];
            float qv = q[idx] * __expf(run) * scale;
            float kgv = k[idx] * __expf(tot - run);
            qs[i * DA_STRIDE + col] = rtf32(qv);
            ks[i * DA_STRIDE + col] = rtf32(k[idx] * __expf(-run));
            qgh[idx] = __float2half(qv);
            kgh[idx] = __float2half(kgv);
        }
    }
    __syncthreads();

#pragma unroll
    for (int tIdx = w * 2; tIdx < w * 2 + 2; tIdx++) {
        int ti = tIdx >> 2, tj = tIdx & 3;
        FragC acc;
        wmma::fill_fragment(acc, 0.0f);
#pragma unroll
        for (int kk = 0; kk < DKd; kk += 8) {
            FragA a; FragBT b;
            wmma::load_matrix_sync(a, &qs[(ti * 16) * DA_STRIDE + kk], DA_STRIDE);
            wmma::load_matrix_sync(b, &ks[(tj * 16) * DA_STRIDE + kk], DA_STRIDE);
            wmma::mma_sync(acc, a, b, acc);
        }
        wmma::store_matrix_sync(&As[(ti * 16) * 72 + tj * 16], acc, 72, wmma::mem_row_major);
    }
    __syncthreads();
    __half* Ab = Ah + (size_t)chh * CH * CH;
    for (int i = tid; i < 64 * 64; i += 256) {
        int r = i >> 6, cc = i & 63;
        Ab[i] = (cc > r) ? __float2half(0.0f) : __float2half(As[r * 72 + cc]);
    }
}

// ---------------- FUSED chunkwise GLA: 128 CTAs, dv-block = 32 (proven config) ----------------
#define S_STRIDE 36
#define SH_STRIDE 40
#define VH_STRIDE 40
#define VF_STRIDE 68
#define U_STRIDE 36
#define FUSED_SMEM_BYTES (128*S_STRIDE*4 + 2*64*VF_STRIDE*4 + 128*U_STRIDE*4 + 2*128*4 \
                          + 128*SH_STRIDE*2 + 64*VH_STRIDE*2)

__global__ __launch_bounds__(256) void gla_fused_kernel(
    const __half* __restrict__ Amat, const __half* __restrict__ qgh,
    const __half* __restrict__ kgh, const float* __restrict__ v,
    const float* __restrict__ glast, float* __restrict__ o)
{
    extern __shared__ char smraw[];
    float*  Ssm  = (float*)smraw;
    float*  Vf   = Ssm + 128 * S_STRIDE;
    float*  Us   = Vf + 2 * 64 * VF_STRIDE;
    float*  sglf = Us + 128 * U_STRIDE;
    __half* Sh   = (__half*)(sglf + 2 * 128);
    __half* Vsh  = Sh + 128 * SH_STRIDE;

    const int id = blockIdx.x;
    const int b = id >> 5, h = (id >> 3) & 3, dvb = id & 7;
    const int tid = threadIdx.x, w = tid >> 5;

    for (int i = tid; i < 128 * S_STRIDE; i += 256) Ssm[i] = 0.0f;
    for (int i = tid; i < 128 * SH_STRIDE / 2; i += 256)
        *((__half2*)Sh + i) = __half2half2(__float2half(0.0f));

    auto issue_load = [&](int n, int buf) {
        const float* vb = v + (size_t)(b * NC + n) * CH * HDV + h * DVd + dvb * 32;
        const float* gl = glast + (size_t)(b * NC + n) * HDK + h * DKd;
#pragma unroll
        for (int cidx = 0; cidx < 2; cidx++) {
            int idx = cidx * 256 + tid;
            int r = idx >> 3, c = idx & 7;
            cpasync16(Vf + buf * 64 * VF_STRIDE + r * VF_STRIDE + c * 4,
                      vb + (size_t)r * HDV + c * 4);
        }
        if (tid < 32) cpasync16(sglf + buf * 128 + tid * 4, gl + tid * 4);
        cp_commit();
    };

    issue_load(0, 0);

    for (int n = 0; n < NC; n++) {
        const int buf = n & 1;
        const int c = b * NC + n;
        const int ch = c * HH + h;
        const size_t t0 = (size_t)c * CH;
        const __half* qgb = qgh + t0 * HDK + h * DKd;
        const __half* kgb = kgh + t0 * HDK + h * DKd;
        const __half* Ab  = Amat + (size_t)ch * CH * CH;
        float* ob         = o + t0 * HDV + h * DVd + dvb * 32;

        asm volatile("cp.async.wait_group 0;\n");
        __syncthreads();

        if (n + 1 < NC) issue_load(n + 1, buf ^ 1);

        {
            int r = tid >> 2, c8 = tid & 3;
            const float* src = Vf + buf * 64 * VF_STRIDE + r * VF_STRIDE + c8 * 8;
            float4 a4 = *(const float4*)src;
            float4 b4 = *(const float4*)(src + 4);
            __half2 h0 = __floats2half2_rn(a4.x, a4.y);
            __half2 h1 = __floats2half2_rn(a4.z, a4.w);
            __half2 h2 = __floats2half2_rn(b4.x, b4.y);
            __half2 h3 = __floats2half2_rn(b4.z, b4.w);
            uint4 u;
            u.x = *(uint32_t*)&h0; u.y = *(uint32_t*)&h1;
            u.z = *(uint32_t*)&h2; u.w = *(uint32_t*)&h3;
            *(uint4*)&Vsh[r * VH_STRIDE + c8 * 8] = u;
        }
        __syncthreads();

        if (w < 4) {
            FragCh acc2[2];
#pragma unroll
            for (int j = 0; j < 2; j++) wmma::fill_fragment(acc2[j], 0.0f);
#pragma unroll
            for (int kk = 0; kk < CH; kk += 16) {
                FragAh a;
                wmma::load_matrix_sync(a, Ab + (size_t)(w * 16) * CH + kk, CH);
#pragma unroll
                for (int j = 0; j < 2; j++) {
                    FragBh bf;
                    wmma::load_matrix_sync(bf, &Vsh[kk * VH_STRIDE + j * 16], VH_STRIDE);
                    wmma::mma_sync(acc2[j], a, bf, acc2[j]);
                }
            }
#pragma unroll
            for (int kk = 0; kk < DKd; kk += 16) {
                FragAh a;
                wmma::load_matrix_sync(a, qgb + (size_t)(w * 16) * HDK + kk, HDK);
#pragma unroll
                for (int j = 0; j < 2; j++) {
                    FragBh bf;
                    wmma::load_matrix_sync(bf, &Sh[kk * SH_STRIDE + j * 16], SH_STRIDE);
                    wmma::mma_sync(acc2[j], a, bf, acc2[j]);
                }
            }
#pragma unroll
            for (int j = 0; j < 2; j++)
                wmma::store_matrix_sync(ob + (size_t)(w * 16) * HDV + j * 16,
                                        acc2[j], HDV, wmma::mem_row_major);
        } else {
            const int wu = w - 4;
            FragCh acc4[2][2];
#pragma unroll
            for (int r = 0; r < 2; r++)
#pragma unroll
                for (int j = 0; j < 2; j++) wmma::fill_fragment(acc4[r][j], 0.0f);
#pragma unroll
            for (int kk = 0; kk < CH; kk += 16) {
                FragAhT a[2];
                FragBh bf[2];
#pragma unroll
                for (int r = 0; r < 2; r++)
                    wmma::load_matrix_sync(a[r], kgb + (size_t)kk * HDK + (2 * wu + r) * 16, HDK);
#pragma unroll
                for (int j = 0; j < 2; j++)
                    wmma::load_matrix_sync(bf[j], &Vsh[kk * VH_STRIDE + j * 16], VH_STRIDE);
#pragma unroll
                for (int r = 0; r < 2; r++)
#pragma unroll
                    for (int j = 0; j < 2; j++)
                        wmma::mma_sync(acc4[r][j], a[r], bf[j], acc4[r][j]);
            }
#pragma unroll
            for (int r = 0; r < 2; r++)
#pragma unroll
                for (int j = 0; j < 2; j++)
                    wmma::store_matrix_sync(&Us[((2 * wu + r) * 16) * U_STRIDE + j * 16],
                                            acc4[r][j], U_STRIDE, wmma::mem_row_major);
        }
        __syncthreads();

        const float* sgl = sglf + buf * 128;
#pragma unroll
        for (int j = 0; j < 16; j++) {
            int i = j * 256 + tid;
            int r = i >> 5, cc = i & 31;
            float s = Ssm[r * S_STRIDE + cc] * sgl[r] + Us[r * U_STRIDE + cc];
            Ssm[r * S_STRIDE + cc] = s;
            Sh[r * SH_STRIDE + cc] = __float2half(s);
        }
    }
}

// ---------------- gated RMSNorm (emits fp16 y) ----------------
__global__ __launch_bounds__(256) void norm_gate_kernel(
    const float* __restrict__ o, const float* __restrict__ g,
    const float* __restrict__ gnw, __half* __restrict__ yh)
{
    int row = blockIdx.x * 8 + (threadIdx.x >> 5);
    int lane = threadIdx.x & 31;
    size_t base = (size_t)row * DVd;
    float v[8];
    float ss = 0.0f;
#pragma unroll
    for (int j = 0; j < 8; j++) {
        v[j] = o[base + lane + j * 32];
        ss += v[j] * v[j];
    }
#pragma unroll
    for (int off = 16; off > 0; off >>= 1)
        ss += __shfl_xor_sync(0xffffffff, ss, off);
    float r = rsqrtf(ss * (1.0f / DVd) + EPS);
#pragma unroll
    for (int j = 0; j < 8; j++) {
        int dv = lane + j * 32;
        float gv = g[base + dv];
        float sw = gv / (1.0f + expf(-gv));
        yh[base + dv] = __float2half(v[j] * r * gnw[dv] * sw);
    }
}

// ---------------- launch ----------------
extern "C" void kernel_launch(void* const* d_in, const int* in_sizes, int n_in,
                              void* d_out, int out_size)
{
    const float* x    = (const float*)d_in[0];
    const float* Wq   = (const float*)d_in[1];
    const float* Wk   = (const float*)d_in[2];
    const float* Wv   = (const float*)d_in[3];
    const float* Wg   = (const float*)d_in[4];
    const float* Wgk1 = (const float*)d_in[5];
    const float* Wgk2 = (const float*)d_in[6];
    const float* bgk2 = (const float*)d_in[7];
    const float* Wo   = (const float*)d_in[8];
    const float* gnw  = (const float*)d_in[9];
    float* out = (float*)d_out;

    __half *xh, *Wqh, *Wkh, *Wvh, *Wgh, *Woh, *yh, *qgh, *kgh, *Ah;
    float *W1t, *q, *k, *v, *g, *gk, *glast, *o;
    cudaGetSymbolAddress((void**)&xh, d_xh);
    cudaGetSymbolAddress((void**)&Wqh, d_Wqh);
    cudaGetSymbolAddress((void**)&Wkh, d_Wkh);
    cudaGetSymbolAddress((void**)&Wvh, d_Wvh);
    cudaGetSymbolAddress((void**)&Wgh, d_Wgh);
    cudaGetSymbolAddress((void**)&Woh, d_Woh);
    cudaGetSymbolAddress((void**)&yh, d_yh);
    cudaGetSymbolAddress((void**)&qgh, d_qgh);
    cudaGetSymbolAddress((void**)&kgh, d_kgh);
    cudaGetSymbolAddress((void**)&Ah, d_Ah);
    cudaGetSymbolAddress((void**)&W1t, d_W1t);
    cudaGetSymbolAddress((void**)&q, d_q);
    cudaGetSymbolAddress((void**)&k, d_k);
    cudaGetSymbolAddress((void**)&v, d_v);
    cudaGetSymbolAddress((void**)&g, d_g);
    cudaGetSymbolAddress((void**)&gk, d_gk);
    cudaGetSymbolAddress((void**)&glast, d_glast);
    cudaGetSymbolAddress((void**)&o, d_o);

    cudaFuncSetAttribute(proj_qkvg_kernel,
                         cudaFuncAttributeMaxDynamicSharedMemorySize, GEMM_SMEM_BYTES);
    cudaFuncSetAttribute(gemm_wo_kernel,
                         cudaFuncAttributeMaxDynamicSharedMemorySize, GEMM_SMEM_BYTES);
    cudaFuncSetAttribute(gla_fused_kernel,
                         cudaFuncAttributeMaxDynamicSharedMemorySize, FUSED_SMEM_BYTES);
    cudaFuncSetAttribute(decayA_kernel,
                         cudaFuncAttributeMaxDynamicSharedMemorySize, DA_SMEM_BYTES);

    // conversions + W1 transpose
    f2h_kernel<<<(BT * DM / 4) / 256, 256>>>((const float4*)x, (uint2*)xh, BT * DM / 4);
    f2h_multi_kernel<<<dim3(1024, 5), 256>>>(
        (const float4*)Wq, (uint2*)Wqh, DM * HDK / 4,
        (const float4*)Wk, (uint2*)Wkh, DM * HDK / 4,
        (const float4*)Wv, (uint2*)Wvh, DM * HDV / 4,
        (const float4*)Wg, (uint2*)Wgh, DM * HDV / 4,
        (const float4*)Wo, (uint2*)Woh, HDV * DM / 4);
    w1_transpose_kernel<<<(LR * DM) / 256, 256>>>(Wgk1, W1t);

    // fused input projections (persistent, 2 CTAs/SM)
    proj_qkvg_kernel<<<PERSIST_CTAS, 256, GEMM_SMEM_BYTES>>>(xh, Wqh, Wkh, Wvh, Wgh, q, k, v, g);

    // fused low-rank gate path
    gk_fused_kernel<<<BT / 8, 256>>>(x, W1t, Wgk2, bgk2, gk);

    // FUSED decay + intra-A
    decayA_kernel<<<NCHUNK * HH, 256, DA_SMEM_BYTES>>>(q, k, gk, qgh, kgh, glast, Ah);

    // fused chunkwise GLA (128 CTAs, dv-block 32 — proven)
    gla_fused_kernel<<<BB * HH * 8, 256, FUSED_SMEM_BYTES>>>(Ah, qgh, kgh, v, glast, o);

    // gated RMSNorm + output projection (persistent)
    norm_gate_kernel<<<(BT * HH) / 8, 256>>>(o, g, gnw, yh);
    gemm_wo_kernel<<<PERSIST_CTAS, 256, GEMM_SMEM_BYTES>>>(yh, Woh, out);
}

// round 17
// speedup vs baseline: 1.0699x; 1.0194x over previous
#include <cuda_runtime.h>
#include <cuda_fp16.h>
#include <mma.h>
#include <cstdint>

using namespace nvcuda;

// ---------------- problem constants ----------------
#define BB 4
#define TT 2048
#define DM 1024
#define HH 4
#define DKd 128
#define DVd 256
#define HDK 512     // H*DK
#define HDV 1024    // H*DV
#define BT  8192    // B*T tokens
#define CH  64      // chunk
#define NC  32      // chunks per sequence
#define NCHUNK 128  // total chunks (B*NC)
#define LR 16       // gate low rank
#define GNORM 16.0f
#define EPS 1e-5f

// ---------------- scratch ----------------
__device__ __half d_xh [BT * DM];
__device__ __half d_Wqh[DM * HDK];
__device__ __half d_Wkh[DM * HDK];
__device__ __half d_Wvh[DM * HDV];
__device__ __half d_Wgh[DM * HDV];
__device__ __half d_Woh[HDV * DM];
__device__ __half d_yh [BT * HDV];
__device__ __half d_qgh[BT * HDK];
__device__ __half d_kgh[BT * HDK];
__device__ __half d_Ah [NCHUNK * HH * CH * CH];
__device__ __half d_oh [BT * HDV];      // fp16 attention output
__device__ float d_W1t [LR * DM];
__device__ float d_q   [BT * HDK];
__device__ float d_k   [BT * HDK];
__device__ float d_v   [BT * HDV];
__device__ float d_g   [BT * HDV];
__device__ float d_gk  [BT * HDK];
__device__ float d_glast[NCHUNK * HDK];

// ---------------- helpers ----------------
__device__ __forceinline__ float rtf32(float x) {
    return wmma::__float_to_tf32(x);
}

typedef wmma::fragment<wmma::matrix_a, 16, 16, 8, wmma::precision::tf32, wmma::row_major> FragA;
typedef wmma::fragment<wmma::matrix_b, 16, 16, 8, wmma::precision::tf32, wmma::col_major> FragBT;
typedef wmma::fragment<wmma::accumulator, 16, 16, 8, float> FragC;

typedef wmma::fragment<wmma::matrix_a, 16, 16, 16, __half, wmma::row_major> FragAh;
typedef wmma::fragment<wmma::matrix_a, 16, 16, 16, __half, wmma::col_major> FragAhT;
typedef wmma::fragment<wmma::matrix_b, 16, 16, 16, __half, wmma::row_major> FragBh;
typedef wmma::fragment<wmma::accumulator, 16, 16, 16, float> FragCh;

__device__ __forceinline__ uint32_t smem_u32(const void* p) {
    return (uint32_t)__cvta_generic_to_shared(p);
}
__device__ __forceinline__ void cpasync16(void* dst, const void* src) {
    asm volatile("cp.async.cg.shared.global [%0], [%1], 16;\n"
                 :: "r"(smem_u32(dst)), "l"(src));
}
__device__ __forceinline__ void cp_commit() {
    asm volatile("cp.async.commit_group;\n");
}

// ---------------- float -> half conversion ----------------
__device__ __forceinline__ void f2h_body(const float4* in, uint2* out, int i) {
    float4 a = in[i];
    __half2 lo = __floats2half2_rn(a.x, a.y);
    __half2 hi = __floats2half2_rn(a.z, a.w);
    uint2 p;
    p.x = *(uint32_t*)&lo;
    p.y = *(uint32_t*)&hi;
    out[i] = p;
}

__global__ __launch_bounds__(256) void f2h_kernel(
    const float4* __restrict__ in, uint2* __restrict__ out, int n4)
{
    int i = blockIdx.x * 256 + threadIdx.x;
    if (i >= n4) return;
    f2h_body(in, out, i);
}

__global__ __launch_bounds__(256) void f2h_multi_kernel(
    const float4* i0, uint2* o0, int n0,
    const float4* i1, uint2* o1, int n1,
    const float4* i2, uint2* o2, int n2,
    const float4* i3, uint2* o3, int n3,
    const float4* i4, uint2* o4, int n4)
{
    const float4* in; uint2* out; int n;
    switch (blockIdx.y) {
        case 0: in = i0; out = o0; n = n0; break;
        case 1: in = i1; out = o1; n = n1; break;
        case 2: in = i2; out = o2; n = n2; break;
        case 3: in = i3; out = o3; n = n3; break;
        default: in = i4; out = o4; n = n4; break;
    }
    int i = blockIdx.x * 256 + threadIdx.x;
    if (i >= n) return;
    f2h_body(in, out, i);
}

// ---------------- W1 transpose ----------------
__global__ __launch_bounds__(256) void w1_transpose_kernel(
    const float* __restrict__ W1, float* __restrict__ W1t)
{
    int i = blockIdx.x * 256 + threadIdx.x;
    int n = i >> 10;
    int j = i & 1023;
    W1t[i] = W1[j * LR + n];
}

// ---------------- fp16 GEMM core: CTA 128x128, 256 threads, BK=32 ----------------
#define AS_STRIDE 40
#define BS_STRIDE 136
#define STAGE_HALFS (128 * AS_STRIDE + 32 * BS_STRIDE)   // 9472
#define GEMM_SMEM_BYTES (3 * STAGE_HALFS * 2)            // 56832

__device__ __forceinline__ void gemm_load_tile_h(
    __half* sm, int buf, const __half* A, int lda, const __half* B, int ldb, int it, int tid)
{
    __half* As = sm + buf * STAGE_HALFS;
    __half* Bs = As + 128 * AS_STRIDE;
    const __half* Ab = A + it * 32;
    const __half* Bb = B + (size_t)it * 32 * ldb;
#pragma unroll
    for (int i = tid; i < 512; i += 256) {
        int r = i >> 2, c = i & 3;
        cpasync16(&As[r * AS_STRIDE + c * 8], Ab + (size_t)r * lda + c * 8);
    }
#pragma unroll
    for (int i = tid; i < 512; i += 256) {
        int r = i >> 4, c = i & 15;
        cpasync16(&Bs[r * BS_STRIDE + c * 8], Bb + (size_t)r * ldb + c * 8);
    }
    cp_commit();
}

__device__ __forceinline__ void gemm128x128_fp16(
    const __half* __restrict__ A, int lda,
    const __half* __restrict__ B, int ldb,
    float* __restrict__ C, int ldc,
    int K, __half* sm)
{
    const int tid = threadIdx.x;
    const int w = tid >> 5;
    const int wr = w >> 1;
    const int wc = w & 1;

    FragCh acc[2][4];
#pragma unroll
    for (int r = 0; r < 2; r++)
#pragma unroll
        for (int c = 0; c < 4; c++) wmma::fill_fragment(acc[r][c], 0.0f);

    const int ntiles = K / 32;

    gemm_load_tile_h(sm, 0, A, lda, B, ldb, 0, tid);
    gemm_load_tile_h(sm, 1, A, lda, B, ldb, 1, tid);

    for (int it = 0; it < ntiles; it++) {
        if (it < ntiles - 1) {
            asm volatile("cp.async.wait_group 1;\n");
        } else {
            asm volatile("cp.async.wait_group 0;\n");
        }
        __syncthreads();
        if (it + 2 < ntiles)
            gemm_load_tile_h(sm, (it + 2) % 3, A, lda, B, ldb, it + 2, tid);

        __half* Ac = sm + (it % 3) * STAGE_HALFS;
        __half* Bc = Ac + 128 * AS_STRIDE;
#pragma unroll
        for (int kk = 0; kk < 32; kk += 16) {
            FragAh af[2];
            FragBh bf[4];
#pragma unroll
            for (int r = 0; r < 2; r++)
                wmma::load_matrix_sync(af[r], &Ac[(wr * 32 + r * 16) * AS_STRIDE + kk], AS_STRIDE);
#pragma unroll
            for (int c = 0; c < 4; c++)
                wmma::load_matrix_sync(bf[c], &Bc[kk * BS_STRIDE + wc * 64 + c * 16], BS_STRIDE);
#pragma unroll
            for (int r = 0; r < 2; r++)
#pragma unroll
                for (int c = 0; c < 4; c++)
                    wmma::mma_sync(acc[r][c], af[r], bf[c], acc[r][c]);
        }
    }
    __syncthreads();

#pragma unroll
    for (int r = 0; r < 2; r++)
#pragma unroll
        for (int c = 0; c < 4; c++)
            wmma::store_matrix_sync(
                C + (size_t)(wr * 32 + r * 16) * ldc + wc * 64 + c * 16,
                acc[r][c], ldc, wmma::mem_row_major);
}

// ---------------- fused q/k/v/g projections (grid-launched, R14 config) ----------------
__global__ __launch_bounds__(256, 2) void proj_qkvg_kernel(
    const __half* __restrict__ xh,
    const __half* __restrict__ Wq, const __half* __restrict__ Wk,
    const __half* __restrict__ Wv, const __half* __restrict__ Wg,
    float* __restrict__ q, float* __restrict__ k,
    float* __restrict__ v, float* __restrict__ g)
{
    extern __shared__ __half smh[];
    const int bn = blockIdx.x;
    const int bm = blockIdx.y;
    const __half* B;
    float* C;
    int n0, ldn;
    if (bn < 4)       { B = Wq; C = q; n0 = bn;      ldn = HDK; }
    else if (bn < 8)  { B = Wk; C = k; n0 = bn - 4;  ldn = HDK; }
    else if (bn < 16) { B = Wv; C = v; n0 = bn - 8;  ldn = HDV; }
    else              { B = Wg; C = g; n0 = bn - 16; ldn = HDV; }
    gemm128x128_fp16(xh + (size_t)bm * 128 * DM, DM,
                     B + n0 * 128, ldn,
                     C + (size_t)bm * 128 * ldn + n0 * 128, ldn,
                     DM, smh);
}

// ---------------- output projection (grid-launched) ----------------
__global__ __launch_bounds__(256, 2) void gemm_wo_kernel(
    const __half* __restrict__ yh, const __half* __restrict__ Wo, float* __restrict__ out)
{
    extern __shared__ __half smh[];
    const int bn = blockIdx.x, bm = blockIdx.y;
    gemm128x128_fp16(yh + (size_t)bm * 128 * HDV, HDV,
                     Wo + bn * 128, DM,
                     out + (size_t)bm * 128 * DM + bn * 128,
                     DM, HDV, smh);
}

// ---------------- fused low-rank gate ----------------
__global__ __launch_bounds__(256) void gk_fused_kernel(
    const float* __restrict__ x, const float* __restrict__ W1t,
    const float* __restrict__ W2, const float* __restrict__ bias,
    float* __restrict__ gk)
{
    int t = blockIdx.x * 8 + (threadIdx.x >> 5);
    int lane = threadIdx.x & 31;
    const float* xr = x + (size_t)t * DM;

    float xreg[32];
#pragma unroll
    for (int i = 0; i < 32; i++) xreg[i] = xr[lane + 32 * i];

    float acc[LR];
#pragma unroll
    for (int n = 0; n < LR; n++) {
        const float* wrow = W1t + (size_t)n * DM;
        float s = 0.0f;
#pragma unroll
        for (int i = 0; i < 32; i++) s += xreg[i] * wrow[lane + 32 * i];
        acc[n] = s;
    }
#pragma unroll
    for (int n = 0; n < LR; n++) {
#pragma unroll
        for (int off = 16; off > 0; off >>= 1)
            acc[n] += __shfl_xor_sync(0xffffffff, acc[n], off);
    }

    float* gkt = gk + (size_t)t * HDK;
#pragma unroll
    for (int j = 0; j < 16; j++) {
        int n = j * 32 + lane;
        float a = bias[n];
#pragma unroll
        for (int kx = 0; kx < LR; kx++) a += acc[kx] * W2[kx * HDK + n];
        float ls = fminf(a, 0.0f) - log1pf(expf(-fabsf(a)));
        gkt[n] = ls * (1.0f / GNORM);
    }
}

// ---------------- FUSED decay + intra-A ----------------
#define DA_STRIDE 132
#define DA_SMEM_BYTES ((2 * 64 * DA_STRIDE + 64 * 72) * 4)   // 86016

__global__ __launch_bounds__(256) void decayA_kernel(
    const float* __restrict__ q, const float* __restrict__ k, const float* __restrict__ gk,
    __half* __restrict__ qgh, __half* __restrict__ kgh,
    float* __restrict__ glast, __half* __restrict__ Ah)
{
    extern __shared__ float dsm[];
    float* qs = dsm;
    float* ks = dsm + 64 * DA_STRIDE;
    float* As = ks + 64 * DA_STRIDE;

    const int chh = blockIdx.x;
    const int c = chh >> 2, h = chh & 3;
    const int tid = threadIdx.x, w = tid >> 5;

    if (tid < 128) {
        const int col = tid;
        size_t base = (size_t)c * CH * HDK + h * DKd + col;
        float tot = 0.0f;
#pragma unroll 8
        for (int i = 0; i < CH; i++) tot += gk[base + (size_t)i * HDK];
        glast[(size_t)c * HDK + h * DKd + col] = __expf(tot);
        const float scale = 0.088388347648318447f;   // 128^-0.5
        float run = 0.0f;
#pragma unroll 4
        for (int i = 0; i < CH; i++) {
            size_t idx = base + (size_t)i * HDK;
            run += gk[idx];
            float qv = q[idx] * __expf(run) * scale;
            float kgv = k[idx] * __expf(tot - run);
            qs[i * DA_STRIDE + col] = rtf32(qv);
            ks[i * DA_STRIDE + col] = rtf32(k[idx] * __expf(-run));
            qgh[idx] = __float2half(qv);
            kgh[idx] = __float2half(kgv);
        }
    }
    __syncthreads();

#pragma unroll
    for (int tIdx = w * 2; tIdx < w * 2 + 2; tIdx++) {
        int ti = tIdx >> 2, tj = tIdx & 3;
        FragC acc;
        wmma::fill_fragment(acc, 0.0f);
#pragma unroll
        for (int kk = 0; kk < DKd; kk += 8) {
            FragA a; FragBT b;
            wmma::load_matrix_sync(a, &qs[(ti * 16) * DA_STRIDE + kk], DA_STRIDE);
            wmma::load_matrix_sync(b, &ks[(tj * 16) * DA_STRIDE + kk], DA_STRIDE);
            wmma::mma_sync(acc, a, b, acc);
        }
        wmma::store_matrix_sync(&As[(ti * 16) * 72 + tj * 16], acc, 72, wmma::mem_row_major);
    }
    __syncthreads();
    __half* Ab = Ah + (size_t)chh * CH * CH;
    for (int i = tid; i < 64 * 64; i += 256) {
        int r = i >> 6, cc = i & 63;
        Ab[i] = (cc > r) ? __float2half(0.0f) : __float2half(As[r * 72 + cc]);
    }
}

// ---------------- FUSED chunkwise GLA: 128 CTAs, dv-block 32, fp16 o output ----------------
#define S_STRIDE 36
#define SH_STRIDE 40
#define VH_STRIDE 40
#define VF_STRIDE 68
#define U_STRIDE 36
#define OS_STRIDE 36
#define FUSED_SMEM_BYTES (128*S_STRIDE*4 + 2*64*VF_STRIDE*4 + 128*U_STRIDE*4 + 2*128*4 \
                          + 64*OS_STRIDE*4 + 128*SH_STRIDE*2 + 64*VH_STRIDE*2)

__global__ __launch_bounds__(256) void gla_fused_kernel(
    const __half* __restrict__ Amat, const __half* __restrict__ qgh,
    const __half* __restrict__ kgh, const float* __restrict__ v,
    const float* __restrict__ glast, __half* __restrict__ oh)
{
    extern __shared__ char smraw[];
    float*  Ssm  = (float*)smraw;
    float*  Vf   = Ssm + 128 * S_STRIDE;
    float*  Us   = Vf + 2 * 64 * VF_STRIDE;
    float*  sglf = Us + 128 * U_STRIDE;
    float*  Os   = sglf + 2 * 128;                  // 64 x 36 staging for o
    __half* Sh   = (__half*)(Os + 64 * OS_STRIDE);
    __half* Vsh  = Sh + 128 * SH_STRIDE;

    const int id = blockIdx.x;
    const int b = id >> 5, h = (id >> 3) & 3, dvb = id & 7;
    const int tid = threadIdx.x, w = tid >> 5;
    const int lane = tid & 31;

    for (int i = tid; i < 128 * S_STRIDE; i += 256) Ssm[i] = 0.0f;
    for (int i = tid; i < 128 * SH_STRIDE / 2; i += 256)
        *((__half2*)Sh + i) = __half2half2(__float2half(0.0f));

    auto issue_load = [&](int n, int buf) {
        const float* vb = v + (size_t)(b * NC + n) * CH * HDV + h * DVd + dvb * 32;
        const float* gl = glast + (size_t)(b * NC + n) * HDK + h * DKd;
#pragma unroll
        for (int cidx = 0; cidx < 2; cidx++) {
            int idx = cidx * 256 + tid;
            int r = idx >> 3, c = idx & 7;
            cpasync16(Vf + buf * 64 * VF_STRIDE + r * VF_STRIDE + c * 4,
                      vb + (size_t)r * HDV + c * 4);
        }
        if (tid < 32) cpasync16(sglf + buf * 128 + tid * 4, gl + tid * 4);
        cp_commit();
    };

    issue_load(0, 0);

    for (int n = 0; n < NC; n++) {
        const int buf = n & 1;
        const int c = b * NC + n;
        const int ch = c * HH + h;
        const size_t t0 = (size_t)c * CH;
        const __half* qgb = qgh + t0 * HDK + h * DKd;
        const __half* kgb = kgh + t0 * HDK + h * DKd;
        const __half* Ab  = Amat + (size_t)ch * CH * CH;
        __half* ob        = oh + t0 * HDV + h * DVd + dvb * 32;

        asm volatile("cp.async.wait_group 0;\n");
        __syncthreads();

        if (n + 1 < NC) issue_load(n + 1, buf ^ 1);

        {
            int r = tid >> 2, c8 = tid & 3;
            const float* src = Vf + buf * 64 * VF_STRIDE + r * VF_STRIDE + c8 * 8;
            float4 a4 = *(const float4*)src;
            float4 b4 = *(const float4*)(src + 4);
            __half2 h0 = __floats2half2_rn(a4.x, a4.y);
            __half2 h1 = __floats2half2_rn(a4.z, a4.w);
            __half2 h2 = __floats2half2_rn(b4.x, b4.y);
            __half2 h3 = __floats2half2_rn(b4.z, b4.w);
            uint4 u;
            u.x = *(uint32_t*)&h0; u.y = *(uint32_t*)&h1;
            u.z = *(uint32_t*)&h2; u.w = *(uint32_t*)&h3;
            *(uint4*)&Vsh[r * VH_STRIDE + c8 * 8] = u;
        }
        __syncthreads();

        if (w < 4) {
            // ---- o = A @ Vsh + qg @ Sh, staged through Os, emitted fp16 ----
            FragCh acc2[2];
#pragma unroll
            for (int j = 0; j < 2; j++) wmma::fill_fragment(acc2[j], 0.0f);
#pragma unroll
            for (int kk = 0; kk < CH; kk += 16) {
                FragAh a;
                wmma::load_matrix_sync(a, Ab + (size_t)(w * 16) * CH + kk, CH);
#pragma unroll
                for (int j = 0; j < 2; j++) {
                    FragBh bf;
                    wmma::load_matrix_sync(bf, &Vsh[kk * VH_STRIDE + j * 16], VH_STRIDE);
                    wmma::mma_sync(acc2[j], a, bf, acc2[j]);
                }
            }
#pragma unroll
            for (int kk = 0; kk < DKd; kk += 16) {
                FragAh a;
                wmma::load_matrix_sync(a, qgb + (size_t)(w * 16) * HDK + kk, HDK);
#pragma unroll
                for (int j = 0; j < 2; j++) {
                    FragBh bf;
                    wmma::load_matrix_sync(bf, &Sh[kk * SH_STRIDE + j * 16], SH_STRIDE);
                    wmma::mma_sync(acc2[j], a, bf, acc2[j]);
                }
            }
#pragma unroll
            for (int j = 0; j < 2; j++)
                wmma::store_matrix_sync(&Os[(w * 16) * OS_STRIDE + j * 16],
                                        acc2[j], OS_STRIDE, wmma::mem_row_major);
            // same warp converts its own 16x32 block to fp16 global (warp-synchronous)
            {
                int r = lane >> 1, cpart = lane & 1;     // 16 rows x 2 col-halves
                const float* srow = &Os[(w * 16 + r) * OS_STRIDE + cpart * 16];
                __half2 hh[8];
#pragma unroll
                for (int i = 0; i < 8; i++)
                    hh[i] = __floats2half2_rn(srow[i * 2], srow[i * 2 + 1]);
                uint4 u0, u1;
                u0.x = *(uint32_t*)&hh[0]; u0.y = *(uint32_t*)&hh[1];
                u0.z = *(uint32_t*)&hh[2]; u0.w = *(uint32_t*)&hh[3];
                u1.x = *(uint32_t*)&hh[4]; u1.y = *(uint32_t*)&hh[5];
                u1.z = *(uint32_t*)&hh[6]; u1.w = *(uint32_t*)&hh[7];
                __half* drow = ob + (size_t)(w * 16 + r) * HDV + cpart * 16;
                *(uint4*)drow = u0;
                *(uint4*)(drow + 8) = u1;
            }
        } else {
            const int wu = w - 4;
            FragCh acc4[2][2];
#pragma unroll
            for (int r = 0; r < 2; r++)
#pragma unroll
                for (int j = 0; j < 2; j++) wmma::fill_fragment(acc4[r][j], 0.0f);
#pragma unroll
            for (int kk = 0; kk < CH; kk += 16) {
                FragAhT a[2];
                FragBh bf[2];
#pragma unroll
                for (int r = 0; r < 2; r++)
                    wmma::load_matrix_sync(a[r], kgb + (size_t)kk * HDK + (2 * wu + r) * 16, HDK);
#pragma unroll
                for (int j = 0; j < 2; j++)
                    wmma::load_matrix_sync(bf[j], &Vsh[kk * VH_STRIDE + j * 16], VH_STRIDE);
#pragma unroll
                for (int r = 0; r < 2; r++)
#pragma unroll
                    for (int j = 0; j < 2; j++)
                        wmma::mma_sync(acc4[r][j], a[r], bf[j], acc4[r][j]);
            }
#pragma unroll
            for (int r = 0; r < 2; r++)
#pragma unroll
                for (int j = 0; j < 2; j++)
                    wmma::store_matrix_sync(&Us[((2 * wu + r) * 16) * U_STRIDE + j * 16],
                                            acc4[r][j], U_STRIDE, wmma::mem_row_major);
        }
        __syncthreads();

        const float* sgl = sglf + buf * 128;
#pragma unroll
        for (int j = 0; j < 16; j++) {
            int i = j * 256 + tid;
            int r = i >> 5, cc = i & 31;
            float s = Ssm[r * S_STRIDE + cc] * sgl[r] + Us[r * U_STRIDE + cc];
            Ssm[r * S_STRIDE + cc] = s;
            Sh[r * SH_STRIDE + cc] = __float2half(s);
        }
    }
}

// ---------------- gated RMSNorm (reads fp16 o, emits fp16 y) ----------------
__global__ __launch_bounds__(256) void norm_gate_kernel(
    const __half* __restrict__ oh, const float* __restrict__ g,
    const float* __restrict__ gnw, __half* __restrict__ yh)
{
    int row = blockIdx.x * 8 + (threadIdx.x >> 5);
    int lane = threadIdx.x & 31;
    size_t base = (size_t)row * DVd;
    float v[8];
    float ss = 0.0f;
#pragma unroll
    for (int j = 0; j < 8; j++) {
        v[j] = __half2float(oh[base + lane + j * 32]);
        ss += v[j] * v[j];
    }
#pragma unroll
    for (int off = 16; off > 0; off >>= 1)
        ss += __shfl_xor_sync(0xffffffff, ss, off);
    float r = rsqrtf(ss * (1.0f / DVd) + EPS);
#pragma unroll
    for (int j = 0; j < 8; j++) {
        int dv = lane + j * 32;
        float gv = g[base + dv];
        float sw = gv / (1.0f + expf(-gv));
        yh[base + dv] = __float2half(v[j] * r * gnw[dv] * sw);
    }
}

// ---------------- launch ----------------
extern "C" void kernel_launch(void* const* d_in, const int* in_sizes, int n_in,
                              void* d_out, int out_size)
{
    const float* x    = (const float*)d_in[0];
    const float* Wq   = (const float*)d_in[1];
    const float* Wk   = (const float*)d_in[2];
    const float* Wv   = (const float*)d_in[3];
    const float* Wg   = (const float*)d_in[4];
    const float* Wgk1 = (const float*)d_in[5];
    const float* Wgk2 = (const float*)d_in[6];
    const float* bgk2 = (const float*)d_in[7];
    const float* Wo   = (const float*)d_in[8];
    const float* gnw  = (const float*)d_in[9];
    float* out = (float*)d_out;

    __half *xh, *Wqh, *Wkh, *Wvh, *Wgh, *Woh, *yh, *qgh, *kgh, *Ah, *oh;
    float *W1t, *q, *k, *v, *g, *gk, *glast;
    cudaGetSymbolAddress((void**)&xh, d_xh);
    cudaGetSymbolAddress((void**)&Wqh, d_Wqh);
    cudaGetSymbolAddress((void**)&Wkh, d_Wkh);
    cudaGetSymbolAddress((void**)&Wvh, d_Wvh);
    cudaGetSymbolAddress((void**)&Wgh, d_Wgh);
    cudaGetSymbolAddress((void**)&Woh, d_Woh);
    cudaGetSymbolAddress((void**)&yh, d_yh);
    cudaGetSymbolAddress((void**)&qgh, d_qgh);
    cudaGetSymbolAddress((void**)&kgh, d_kgh);
    cudaGetSymbolAddress((void**)&Ah, d_Ah);
    cudaGetSymbolAddress((void**)&oh, d_oh);
    cudaGetSymbolAddress((void**)&W1t, d_W1t);
    cudaGetSymbolAddress((void**)&q, d_q);
    cudaGetSymbolAddress((void**)&k, d_k);
    cudaGetSymbolAddress((void**)&v, d_v);
    cudaGetSymbolAddress((void**)&g, d_g);
    cudaGetSymbolAddress((void**)&gk, d_gk);
    cudaGetSymbolAddress((void**)&glast, d_glast);

    cudaFuncSetAttribute(proj_qkvg_kernel,
                         cudaFuncAttributeMaxDynamicSharedMemorySize, GEMM_SMEM_BYTES);
    cudaFuncSetAttribute(gemm_wo_kernel,
                         cudaFuncAttributeMaxDynamicSharedMemorySize, GEMM_SMEM_BYTES);
    cudaFuncSetAttribute(gla_fused_kernel,
                         cudaFuncAttributeMaxDynamicSharedMemorySize, FUSED_SMEM_BYTES);
    cudaFuncSetAttribute(decayA_kernel,
                         cudaFuncAttributeMaxDynamicSharedMemorySize, DA_SMEM_BYTES);

    // conversions + W1 transpose
    f2h_kernel<<<(BT * DM / 4) / 256, 256>>>((const float4*)x, (uint2*)xh, BT * DM / 4);
    f2h_multi_kernel<<<dim3(1024, 5), 256>>>(
        (const float4*)Wq, (uint2*)Wqh, DM * HDK / 4,
        (const float4*)Wk, (uint2*)Wkh, DM * HDK / 4,
        (const float4*)Wv, (uint2*)Wvh, DM * HDV / 4,
        (const float4*)Wg, (uint2*)Wgh, DM * HDV / 4,
        (const float4*)Wo, (uint2*)Woh, HDV * DM / 4);
    w1_transpose_kernel<<<(LR * DM) / 256, 256>>>(Wgk1, W1t);

    // fused input projections (grid-launched, R14 config)
    proj_qkvg_kernel<<<dim3(24, BT / 128), 256, GEMM_SMEM_BYTES>>>(xh, Wqh, Wkh, Wvh, Wgh, q, k, v, g);

    // fused low-rank gate path
    gk_fused_kernel<<<BT / 8, 256>>>(x, W1t, Wgk2, bgk2, gk);

    // FUSED decay + intra-A
    decayA_kernel<<<NCHUNK * HH, 256, DA_SMEM_BYTES>>>(q, k, gk, qgh, kgh, glast, Ah);

    // fused chunkwise GLA (fp16 o output)
    gla_fused_kernel<<<BB * HH * 8, 256, FUSED_SMEM_BYTES>>>(Ah, qgh, kgh, v, glast, oh);

    // gated RMSNorm + output projection (grid-launched)
    norm_gate_kernel<<<(BT * HH) / 8, 256>>>(oh, g, gnw, yh);
    gemm_wo_kernel<<<dim3(DM / 128, BT / 128), 256, GEMM_SMEM_BYTES>>>(yh, Woh, out);
}